// round 5
// baseline (speedup 1.0000x reference)
#include <cuda_runtime.h>
#include <math.h>
#include <float.h>

// Problem constants
#define B_    2
#define T_    2048
#define DM_   2048
#define HQ_   32
#define HKV_  8
#define HD_   64

// Scratch (no allocs allowed -> __device__ globals)
__device__ float g_Q[(size_t)B_ * HQ_  * T_ * HD_];   // [B][HQ][T][HD], rope'd
__device__ float g_K[(size_t)B_ * HKV_ * T_ * HD_];   // [B][HKV][T][HD], rope'd
__device__ float g_V[(size_t)B_ * HKV_ * T_ * HD_];   // [B][HKV][T][HD]
__device__ float g_O[(size_t)B_ * T_ * DM_];          // [B][T][HQ*HD] attention out

// log2(10000)
#define LOG2_THETA 13.287712379549449

// ============================================================================
// Kernel 1: QKV projection + fused RoPE.
// C[m][j] = sum_d x[m][d] * Wcat[j][d],  m = b*T + t, j in [0,3072)
// Tiles: BM=128, BN=64, BK=16, 128 threads, 8x8 micro-tile.
// nb < 32 -> WQ head nb; nb < 40 -> WK head nb-32; else WV head nb-40.
// ============================================================================
__global__ __launch_bounds__(128)
void qkv_proj_kernel(const float* __restrict__ x, const int* __restrict__ pos,
                     const float* __restrict__ WQ, const float* __restrict__ WK,
                     const float* __restrict__ WV)
{
    __shared__ float As[16][128];   // [k][m]
    __shared__ float Bs[16][64];    // [k][j]

    const int nb = blockIdx.x;          // 0..47
    const int m0 = blockIdx.y * 128;    // row tile base

    const float* W;
    int head, which;
    if (nb < 32)      { W = WQ + (size_t)nb * 64 * DM_;        head = nb;      which = 0; }
    else if (nb < 40) { W = WK + (size_t)(nb - 32) * 64 * DM_; head = nb - 32; which = 1; }
    else              { W = WV + (size_t)(nb - 40) * 64 * DM_; head = nb - 40; which = 2; }

    const int tid = threadIdx.x;
    const int ty = tid >> 3, tx = tid & 7;
    const int r0 = ty * 8, c0 = tx * 8;

    float acc[8][8];
#pragma unroll
    for (int i = 0; i < 8; i++)
#pragma unroll
        for (int j = 0; j < 8; j++) acc[i][j] = 0.f;

    const float* aptr = x + (size_t)(m0 + tid) * DM_;         // 1 row per thread
    const int brow = tid >> 1;
    const int blk  = (tid & 1) * 8;
    const float* bptr = W + (size_t)brow * DM_ + blk;

    for (int k0 = 0; k0 < DM_; k0 += 16) {
        float4 a4[4];
#pragma unroll
        for (int v = 0; v < 4; v++)
            a4[v] = *(const float4*)(aptr + k0 + 4 * v);
        float4 b0 = *(const float4*)(bptr + k0);
        float4 b1 = *(const float4*)(bptr + k0 + 4);
        __syncthreads();
#pragma unroll
        for (int v = 0; v < 4; v++) {
            As[4 * v + 0][tid] = a4[v].x;
            As[4 * v + 1][tid] = a4[v].y;
            As[4 * v + 2][tid] = a4[v].z;
            As[4 * v + 3][tid] = a4[v].w;
        }
        Bs[blk + 0][brow] = b0.x; Bs[blk + 1][brow] = b0.y;
        Bs[blk + 2][brow] = b0.z; Bs[blk + 3][brow] = b0.w;
        Bs[blk + 4][brow] = b1.x; Bs[blk + 5][brow] = b1.y;
        Bs[blk + 6][brow] = b1.z; Bs[blk + 7][brow] = b1.w;
        __syncthreads();
#pragma unroll 8
        for (int kk = 0; kk < 16; kk++) {
            float4 av0 = *(const float4*)&As[kk][r0];
            float4 av1 = *(const float4*)&As[kk][r0 + 4];
            float4 bv0 = *(const float4*)&Bs[kk][c0];
            float4 bv1 = *(const float4*)&Bs[kk][c0 + 4];
            float a[8] = {av0.x, av0.y, av0.z, av0.w, av1.x, av1.y, av1.z, av1.w};
            float b[8] = {bv0.x, bv0.y, bv0.z, bv0.w, bv1.x, bv1.y, bv1.z, bv1.w};
#pragma unroll
            for (int i = 0; i < 8; i++)
#pragma unroll
                for (int j = 0; j < 8; j++)
                    acc[i][j] = fmaf(a[i], b[j], acc[i][j]);
        }
    }

    // Epilogue: scatter + rope (double-precision angles for accuracy headroom)
    double invf[4];
    if (which != 2) {
#pragma unroll
        for (int u = 0; u < 4; u++)
            invf[u] = exp2(-((double)(c0 + 2 * u)) * (LOG2_THETA / 64.0));
    }

#pragma unroll
    for (int i = 0; i < 8; i++) {
        int m = m0 + r0 + i;
        int bb = m / T_;
        int t  = m - bb * T_;
        if (which == 2) {
            float* dst = g_V + (((size_t)bb * HKV_ + head) * T_ + t) * HD_ + c0;
            *(float4*)(dst)     = make_float4(acc[i][0], acc[i][1], acc[i][2], acc[i][3]);
            *(float4*)(dst + 4) = make_float4(acc[i][4], acc[i][5], acc[i][6], acc[i][7]);
        } else {
            int p = pos[t];
            float r_[8];
#pragma unroll
            for (int u = 0; u < 4; u++) {
                double sn, cs;
                sincos((double)p * invf[u], &sn, &cs);
                float fc = (float)cs, fs = (float)sn;
                float fe = acc[i][2 * u], fo = acc[i][2 * u + 1];
                r_[2 * u]     = fe * fc - fo * fs;
                r_[2 * u + 1] = fe * fs + fo * fc;
            }
            float* dst = (which == 0)
                ? g_Q + (((size_t)bb * HQ_  + head) * T_ + t) * HD_ + c0
                : g_K + (((size_t)bb * HKV_ + head) * T_ + t) * HD_ + c0;
            *(float4*)(dst)     = make_float4(r_[0], r_[1], r_[2], r_[3]);
            *(float4*)(dst + 4) = make_float4(r_[4], r_[5], r_[6], r_[7]);
        }
    }
}

// ============================================================================
// Kernel 2: causal GQA flash attention, fp32.
// Block: 128 threads, BM=128 queries x BN=64 keys, HD=64.
// grid = (T/128, HQ, B). blockIdx.x reversed -> heavy (late) q-tiles first.
// 99.8 KB dynamic smem -> 2 CTAs/SM.
// ============================================================================
#define ATTN_SMEM_FLOATS (64*128 + 64*64 + 64*68 + 128*65)

__global__ __launch_bounds__(128, 2)
void attn_kernel()
{
    extern __shared__ float sm[];
    float* Qs = sm;                        // [d][r]  64 x 128
    float* Ks = Qs + 64 * 128;             // [d][n]  64 x 64
    float* Vs = Ks + 64 * 64;              // [n][d]  64 x 68 (padded)
    float* Ps = Vs + 64 * 68;              // [r][n]  128 x 65 (padded)

    const int qt = (int)gridDim.x - 1 - (int)blockIdx.x;   // 0..15
    const int h  = blockIdx.y;
    const int bb = blockIdx.z;
    const int hk = h >> 2;                                 // G = 4

    const int tid = threadIdx.x;
    const int ty = tid >> 3, tx = tid & 7;
    const int r0 = ty * 8, c0 = tx * 8;

    // Load Q tile (pre-scaled by 1/sqrt(HD)=0.125), transposed [d][r]
    {
        const float* qsrc = g_Q + (((size_t)bb * HQ_ + h) * T_ + (size_t)qt * 128 + tid) * HD_;
#pragma unroll
        for (int v = 0; v < 16; v++) {
            float4 q4 = *(const float4*)(qsrc + 4 * v);
            Qs[(4 * v + 0) * 128 + tid] = q4.x * 0.125f;
            Qs[(4 * v + 1) * 128 + tid] = q4.y * 0.125f;
            Qs[(4 * v + 2) * 128 + tid] = q4.z * 0.125f;
            Qs[(4 * v + 3) * 128 + tid] = q4.w * 0.125f;
        }
    }

    float O[8][8];
#pragma unroll
    for (int i = 0; i < 8; i++)
#pragma unroll
        for (int j = 0; j < 8; j++) O[i][j] = 0.f;
    float m_st[8], l_st[8];
#pragma unroll
    for (int i = 0; i < 8; i++) { m_st[i] = -FLT_MAX; l_st[i] = 0.f; }

    const float* kbase = g_K + ((size_t)bb * HKV_ + hk) * T_ * HD_;
    const float* vbase = g_V + ((size_t)bb * HKV_ + hk) * T_ * HD_;

    const int nrow  = tid >> 1;
    const int dpart = (tid & 1) * 32;
    const int ktmax = 2 * qt + 1;

    for (int kt = 0; kt <= ktmax; kt++) {
        __syncthreads();   // smem WAR vs previous iteration's reads
        // Load K (transposed [d][n]) and V ([n][d], stride 68)
        {
            const float* ksrc = kbase + ((size_t)kt * 64 + nrow) * HD_ + dpart;
            const float* vsrc = vbase + ((size_t)kt * 64 + nrow) * HD_ + dpart;
#pragma unroll
            for (int v = 0; v < 8; v++) {
                float4 k4 = *(const float4*)(ksrc + 4 * v);
                int d = dpart + 4 * v;
                Ks[(d + 0) * 64 + nrow] = k4.x;
                Ks[(d + 1) * 64 + nrow] = k4.y;
                Ks[(d + 2) * 64 + nrow] = k4.z;
                Ks[(d + 3) * 64 + nrow] = k4.w;
                *(float4*)&Vs[nrow * 68 + dpart + 4 * v] = *(const float4*)(vsrc + 4 * v);
            }
        }
        __syncthreads();

        // GEMM1: S = Q * K^T  (8x8 per thread)
        float S[8][8];
#pragma unroll
        for (int i = 0; i < 8; i++)
#pragma unroll
            for (int j = 0; j < 8; j++) S[i][j] = 0.f;
#pragma unroll 8
        for (int kk = 0; kk < 64; kk++) {
            float4 a0 = *(const float4*)&Qs[kk * 128 + r0];
            float4 a1 = *(const float4*)&Qs[kk * 128 + r0 + 4];
            float4 b0 = *(const float4*)&Ks[kk * 64 + c0];
            float4 b1 = *(const float4*)&Ks[kk * 64 + c0 + 4];
            float a[8] = {a0.x, a0.y, a0.z, a0.w, a1.x, a1.y, a1.z, a1.w};
            float b[8] = {b0.x, b0.y, b0.z, b0.w, b1.x, b1.y, b1.z, b1.w};
#pragma unroll
            for (int i = 0; i < 8; i++)
#pragma unroll
                for (int j = 0; j < 8; j++)
                    S[i][j] = fmaf(a[i], b[j], S[i][j]);
        }

        // Causal mask (only tiles overlapping the diagonal)
        if (kt >= 2 * qt) {
            int qg0 = qt * 128 + r0;
            int kg0 = kt * 64 + c0;
#pragma unroll
            for (int i = 0; i < 8; i++)
#pragma unroll
                for (int j = 0; j < 8; j++)
                    if (kg0 + j > qg0 + i) S[i][j] = -FLT_MAX;
        }

        // Online softmax (row group = 8 lanes sharing ty; xor 1/2/4)
#pragma unroll
        for (int i = 0; i < 8; i++) {
            float mx = S[i][0];
#pragma unroll
            for (int j = 1; j < 8; j++) mx = fmaxf(mx, S[i][j]);
            mx = fmaxf(mx, __shfl_xor_sync(0xffffffffu, mx, 1));
            mx = fmaxf(mx, __shfl_xor_sync(0xffffffffu, mx, 2));
            mx = fmaxf(mx, __shfl_xor_sync(0xffffffffu, mx, 4));
            float nm = fmaxf(m_st[i], mx);
            float sum = 0.f;
#pragma unroll
            for (int j = 0; j < 8; j++) {
                S[i][j] = __expf(S[i][j] - nm);
                sum += S[i][j];
            }
            sum += __shfl_xor_sync(0xffffffffu, sum, 1);
            sum += __shfl_xor_sync(0xffffffffu, sum, 2);
            sum += __shfl_xor_sync(0xffffffffu, sum, 4);
            float corr = __expf(m_st[i] - nm);
            m_st[i] = nm;
            l_st[i] = l_st[i] * corr + sum;
#pragma unroll
            for (int j = 0; j < 8; j++) O[i][j] *= corr;
            float* prow = &Ps[(r0 + i) * 65 + c0];
#pragma unroll
            for (int j = 0; j < 8; j++) prow[j] = S[i][j];
        }
        __syncthreads();

        // GEMM2: O += P * V
#pragma unroll 4
        for (int n = 0; n < 64; n++) {
            float4 v0 = *(const float4*)&Vs[n * 68 + c0];
            float4 v1 = *(const float4*)&Vs[n * 68 + c0 + 4];
            float vv[8] = {v0.x, v0.y, v0.z, v0.w, v1.x, v1.y, v1.z, v1.w};
#pragma unroll
            for (int i = 0; i < 8; i++) {
                float a = Ps[(r0 + i) * 65 + n];
#pragma unroll
                for (int j = 0; j < 8; j++)
                    O[i][j] = fmaf(a, vv[j], O[i][j]);
            }
        }
    }

    // Finalize: O /= l, write [B][T][HQ*HD]
#pragma unroll
    for (int i = 0; i < 8; i++) {
        float inv = 1.0f / l_st[i];
        float* dst = g_O + ((size_t)bb * T_ + (size_t)qt * 128 + r0 + i) * DM_ + h * HD_ + c0;
        *(float4*)(dst)     = make_float4(O[i][0] * inv, O[i][1] * inv, O[i][2] * inv, O[i][3] * inv);
        *(float4*)(dst + 4) = make_float4(O[i][4] * inv, O[i][5] * inv, O[i][6] * inv, O[i][7] * inv);
    }
}

// ============================================================================
// Kernel 3: output projection. out[m][n] = sum_k g_O[m][k] * WO[n][k]
// Same tiling as kernel 1. grid = (2048/64, 4096/128).
// ============================================================================
__global__ __launch_bounds__(128)
void out_proj_kernel(const float* __restrict__ WO, float* __restrict__ out)
{
    __shared__ float As[16][128];
    __shared__ float Bs[16][64];

    const int n0 = blockIdx.x * 64;
    const int m0 = blockIdx.y * 128;

    const int tid = threadIdx.x;
    const int ty = tid >> 3, tx = tid & 7;
    const int r0 = ty * 8, c0 = tx * 8;

    float acc[8][8];
#pragma unroll
    for (int i = 0; i < 8; i++)
#pragma unroll
        for (int j = 0; j < 8; j++) acc[i][j] = 0.f;

    const float* aptr = g_O + (size_t)(m0 + tid) * DM_;
    const int brow = tid >> 1;
    const int blk  = (tid & 1) * 8;
    const float* bptr = WO + (size_t)(n0 + brow) * DM_ + blk;

    for (int k0 = 0; k0 < DM_; k0 += 16) {
        float4 a4[4];
#pragma unroll
        for (int v = 0; v < 4; v++)
            a4[v] = *(const float4*)(aptr + k0 + 4 * v);
        float4 b0 = *(const float4*)(bptr + k0);
        float4 b1 = *(const float4*)(bptr + k0 + 4);
        __syncthreads();
#pragma unroll
        for (int v = 0; v < 4; v++) {
            As[4 * v + 0][tid] = a4[v].x;
            As[4 * v + 1][tid] = a4[v].y;
            As[4 * v + 2][tid] = a4[v].z;
            As[4 * v + 3][tid] = a4[v].w;
        }
        Bs[blk + 0][brow] = b0.x; Bs[blk + 1][brow] = b0.y;
        Bs[blk + 2][brow] = b0.z; Bs[blk + 3][brow] = b0.w;
        Bs[blk + 4][brow] = b1.x; Bs[blk + 5][brow] = b1.y;
        Bs[blk + 6][brow] = b1.z; Bs[blk + 7][brow] = b1.w;
        __syncthreads();
#pragma unroll 8
        for (int kk = 0; kk < 16; kk++) {
            float4 av0 = *(const float4*)&As[kk][r0];
            float4 av1 = *(const float4*)&As[kk][r0 + 4];
            float4 bv0 = *(const float4*)&Bs[kk][c0];
            float4 bv1 = *(const float4*)&Bs[kk][c0 + 4];
            float a[8] = {av0.x, av0.y, av0.z, av0.w, av1.x, av1.y, av1.z, av1.w};
            float b[8] = {bv0.x, bv0.y, bv0.z, bv0.w, bv1.x, bv1.y, bv1.z, bv1.w};
#pragma unroll
            for (int i = 0; i < 8; i++)
#pragma unroll
                for (int j = 0; j < 8; j++)
                    acc[i][j] = fmaf(a[i], b[j], acc[i][j]);
        }
    }

#pragma unroll
    for (int i = 0; i < 8; i++) {
        float* dst = out + (size_t)(m0 + r0 + i) * DM_ + n0 + c0;
        *(float4*)(dst)     = make_float4(acc[i][0], acc[i][1], acc[i][2], acc[i][3]);
        *(float4*)(dst + 4) = make_float4(acc[i][4], acc[i][5], acc[i][6], acc[i][7]);
    }
}

// ============================================================================
extern "C" void kernel_launch(void* const* d_in, const int* in_sizes, int n_in,
                              void* d_out, int out_size)
{
    const float* x   = (const float*)d_in[0];
    const int*   pos = (const int*)  d_in[1];
    const float* WQ  = (const float*)d_in[2];
    const float* WK  = (const float*)d_in[3];
    const float* WV  = (const float*)d_in[4];
    const float* WO  = (const float*)d_in[5];
    float* out = (float*)d_out;

    // ~99.8 KB dynamic smem for the attention kernel (idempotent, non-stream op)
    cudaFuncSetAttribute(attn_kernel, cudaFuncAttributeMaxDynamicSharedMemorySize,
                         ATTN_SMEM_FLOATS * (int)sizeof(float));

    dim3 gProj(48, (B_ * T_) / 128);          // (48, 32)
    qkv_proj_kernel<<<gProj, 128>>>(x, pos, WQ, WK, WV);

    dim3 gAttn(T_ / 128, HQ_, B_);            // (16, 32, 2)
    attn_kernel<<<gAttn, 128, ATTN_SMEM_FLOATS * (int)sizeof(float)>>>();

    dim3 gOut(DM_ / 64, (B_ * T_) / 128);     // (32, 32)
    out_proj_kernel<<<gOut, 128>>>(WO, out);
}

// round 7
// speedup vs baseline: 1.5659x; 1.5659x over previous
#include <cuda_runtime.h>
#include <cuda_bf16.h>
#include <math.h>
#include <float.h>
#include <stdint.h>

// Problem constants
#define B_    2
#define T_    2048
#define DM_   2048
#define HQ_   32
#define HKV_  8
#define HD_   64
#define LOG2_THETA 13.287712379549449

// fp32 scratch
__device__ float g_Q[(size_t)B_ * HQ_  * T_ * HD_];
__device__ float g_K[(size_t)B_ * HKV_ * T_ * HD_];
__device__ float g_V[(size_t)B_ * HKV_ * T_ * HD_];

// bf16 hi/lo split buffers
__device__ __nv_bfloat16 g_xhi[(size_t)4096 * 2048];
__device__ __nv_bfloat16 g_xlo[(size_t)4096 * 2048];
__device__ __nv_bfloat16 g_Whi[(size_t)3072 * 2048];   // WQ|WK|WV rows
__device__ __nv_bfloat16 g_Wlo[(size_t)3072 * 2048];
__device__ __nv_bfloat16 g_WOhi[(size_t)2048 * 2048];
__device__ __nv_bfloat16 g_WOlo[(size_t)2048 * 2048];
__device__ __nv_bfloat16 g_Ohi[(size_t)4096 * 2048];   // attention out
__device__ __nv_bfloat16 g_Olo[(size_t)4096 * 2048];

// ============================================================================
// PTX helpers (legacy tensor path: plain PTX, valid on compute_103)
// ============================================================================
__device__ __forceinline__ uint32_t smem_u32(const void* p) {
    uint32_t a;
    asm("{ .reg .u64 t; cvta.to.shared.u64 t, %1; cvt.u32.u64 %0, t; }"
        : "=r"(a) : "l"(p));
    return a;
}
__device__ __forceinline__ void ldsm_x4(uint32_t& r0, uint32_t& r1,
                                        uint32_t& r2, uint32_t& r3, uint32_t a) {
    asm volatile("ldmatrix.sync.aligned.m8n8.x4.shared.b16 {%0,%1,%2,%3}, [%4];"
                 : "=r"(r0), "=r"(r1), "=r"(r2), "=r"(r3) : "r"(a));
}
__device__ __forceinline__ void mma16816(float* d, const uint32_t* a, const uint32_t* b) {
    asm volatile(
        "mma.sync.aligned.m16n8k16.row.col.f32.bf16.bf16.f32 "
        "{%0,%1,%2,%3}, {%4,%5,%6,%7}, {%8,%9}, {%0,%1,%2,%3};"
        : "+f"(d[0]), "+f"(d[1]), "+f"(d[2]), "+f"(d[3])
        : "r"(a[0]), "r"(a[1]), "r"(a[2]), "r"(a[3]), "r"(b[0]), "r"(b[1]));
}
__device__ __forceinline__ void split1(float v, __nv_bfloat16& h, __nv_bfloat16& l) {
    h = __float2bfloat16_rn(v);
    l = __float2bfloat16_rn(v - __bfloat162float(h));
}

// ============================================================================
// Kernel 0: fp32 -> (hi, lo) bf16 conversion for x, WQ|WK|WV, WO.
// One float4 per thread; segment chosen by global element index.
// ============================================================================
#define NE_X   8388608ull     // 4096*2048
#define NE_WQ  4194304ull     // 2048*2048
#define NE_WKV 1048576ull     // 512*2048
#define NE_WO  4194304ull
#define CVT_TOTAL_F4 4718592  // (NE_X+NE_WQ+2*NE_WKV+NE_WO)/4

__global__ __launch_bounds__(256)
void cvt_kernel(const float* __restrict__ x,  const float* __restrict__ WQ,
                const float* __restrict__ WK, const float* __restrict__ WV,
                const float* __restrict__ WO)
{
    const size_t e = ((size_t)blockIdx.x * 256 + threadIdx.x) * 4;
    const float* src; __nv_bfloat16 *dh, *dl; size_t off;
    if (e < NE_X)                          { src = x;  dh = g_xhi;            dl = g_xlo;            off = e; }
    else if (e < NE_X + NE_WQ)             { src = WQ; dh = g_Whi;            dl = g_Wlo;            off = e - NE_X; }
    else if (e < NE_X + NE_WQ + NE_WKV)    { src = WK; dh = g_Whi + 4194304;  dl = g_Wlo + 4194304;  off = e - NE_X - NE_WQ; }
    else if (e < NE_X + NE_WQ + 2*NE_WKV)  { src = WV; dh = g_Whi + 5242880;  dl = g_Wlo + 5242880;  off = e - NE_X - NE_WQ - NE_WKV; }
    else                                   { src = WO; dh = g_WOhi;           dl = g_WOlo;           off = e - NE_X - NE_WQ - 2*NE_WKV; }
    float4 v = *(const float4*)(src + off);
    __nv_bfloat16 h0, h1, h2, h3, l0, l1, l2, l3;
    split1(v.x, h0, l0); split1(v.y, h1, l1); split1(v.z, h2, l2); split1(v.w, h3, l3);
    uint2 uh, ul;
    uh.x = (uint32_t)__bfloat16_as_ushort(h0) | ((uint32_t)__bfloat16_as_ushort(h1) << 16);
    uh.y = (uint32_t)__bfloat16_as_ushort(h2) | ((uint32_t)__bfloat16_as_ushort(h3) << 16);
    ul.x = (uint32_t)__bfloat16_as_ushort(l0) | ((uint32_t)__bfloat16_as_ushort(l1) << 16);
    ul.y = (uint32_t)__bfloat16_as_ushort(l2) | ((uint32_t)__bfloat16_as_ushort(l3) << 16);
    *(uint2*)(dh + off) = uh;
    *(uint2*)(dl + off) = ul;
}

// ============================================================================
// mma.sync split-fp32 GEMM:  D[128x128] = A[128xK] * B[128xK]^T, K=2048.
// 256 threads = 8 warps (4x2), warp tile 32x64, BK=32, padded-40 smem rows.
// 3 passes per K16 step: hi*hi + hi*lo + lo*hi (fp32 accum in registers).
// MODE 0: QKV proj (+RoPE epilogue, scatter to g_Q/g_K/g_V fp32).
// MODE 1: out proj (A = g_Ohi/lo), fp32 result to outp.
// ============================================================================
#define SPAD 40   // bf16 row stride (80 B): conflict-free ldmatrix

template <int MODE>
__global__ __launch_bounds__(256)
void gemm_mma_kernel(const int* __restrict__ pos, float* __restrict__ outp)
{
    __shared__ __align__(16) __nv_bfloat16 sA[2][128 * SPAD];  // [hi|lo]
    __shared__ __align__(16) __nv_bfloat16 sB[2][128 * SPAD];

    const int j0 = blockIdx.x * 128;
    const int m0 = blockIdx.y * 128;
    const int tid = threadIdx.x;
    const int wid = tid >> 5, lane = tid & 31;

    const __nv_bfloat16* Ahi = (MODE == 0) ? g_xhi : g_Ohi;
    const __nv_bfloat16* Alo = (MODE == 0) ? g_xlo : g_Olo;
    const __nv_bfloat16* Bhi = ((MODE == 0) ? g_Whi : g_WOhi) + (size_t)j0 * DM_;
    const __nv_bfloat16* Blo = ((MODE == 0) ? g_Wlo : g_WOlo) + (size_t)j0 * DM_;

    const int lrow = tid >> 1;              // 0..127
    const int lcol = (tid & 1) * 16;        // 0 or 16 (bf16 elems)
    const size_t aoff = (size_t)(m0 + lrow) * DM_ + lcol;
    const size_t boff = (size_t)lrow * DM_ + lcol;

    const int wm = (wid & 3) * 32;          // warp row base
    const int wn = (wid >> 2) * 64;         // warp col base (B row)

    float acc[2][8][4];
#pragma unroll
    for (int mt = 0; mt < 2; mt++)
#pragma unroll
        for (int nt = 0; nt < 8; nt++)
#pragma unroll
            for (int q = 0; q < 4; q++) acc[mt][nt][q] = 0.f;

    const uint32_t aB = smem_u32(sA);
    const uint32_t bB = smem_u32(sB);
    const int sidx = lrow * SPAD + lcol;    // smem store index (bf16)

    // Prefetch chunk 0
    uint4 pa0 = *(const uint4*)(Ahi + aoff);
    uint4 pa1 = *(const uint4*)(Ahi + aoff + 8);
    uint4 pa2 = *(const uint4*)(Alo + aoff);
    uint4 pa3 = *(const uint4*)(Alo + aoff + 8);
    uint4 pb0 = *(const uint4*)(Bhi + boff);
    uint4 pb1 = *(const uint4*)(Bhi + boff + 8);
    uint4 pb2 = *(const uint4*)(Blo + boff);
    uint4 pb3 = *(const uint4*)(Blo + boff + 8);

    for (int kc = 0; kc < DM_ / 32; kc++) {
        __syncthreads();
        *(uint4*)&sA[0][sidx]     = pa0;
        *(uint4*)&sA[0][sidx + 8] = pa1;
        *(uint4*)&sA[1][sidx]     = pa2;
        *(uint4*)&sA[1][sidx + 8] = pa3;
        *(uint4*)&sB[0][sidx]     = pb0;
        *(uint4*)&sB[0][sidx + 8] = pb1;
        *(uint4*)&sB[1][sidx]     = pb2;
        *(uint4*)&sB[1][sidx + 8] = pb3;
        __syncthreads();

        if (kc + 1 < DM_ / 32) {            // prefetch next chunk
            const size_t nk = (size_t)(kc + 1) * 32;
            pa0 = *(const uint4*)(Ahi + aoff + nk);
            pa1 = *(const uint4*)(Ahi + aoff + nk + 8);
            pa2 = *(const uint4*)(Alo + aoff + nk);
            pa3 = *(const uint4*)(Alo + aoff + nk + 8);
            pb0 = *(const uint4*)(Bhi + boff + nk);
            pb1 = *(const uint4*)(Bhi + boff + nk + 8);
            pb2 = *(const uint4*)(Blo + boff + nk);
            pb3 = *(const uint4*)(Blo + boff + nk + 8);
        }

#pragma unroll
        for (int ks = 0; ks < 2; ks++) {
            // B fragments: hi + lo for all 8 n-tiles (x4 covers an nt-pair)
            uint32_t bh[8][2], bl[8][2];
            const int brow = wn + ((lane >> 4) & 1) * 8 + (lane & 7);
            const int bcol = ks * 16 + ((lane >> 3) & 1) * 8;
#pragma unroll
            for (int p = 0; p < 4; p++) {
                const uint32_t off = (uint32_t)((brow + p * 16) * SPAD + bcol) * 2u;
                ldsm_x4(bh[2*p][0], bh[2*p][1], bh[2*p+1][0], bh[2*p+1][1], bB + off);
                ldsm_x4(bl[2*p][0], bl[2*p][1], bl[2*p+1][0], bl[2*p+1][1],
                        bB + 128 * SPAD * 2 + off);
            }
            const int arow = wm + (lane & 15);
            const int acol = ks * 16 + (lane >> 4) * 8;
#pragma unroll
            for (int mt = 0; mt < 2; mt++) {
                uint32_t ah[4], al[4];
                const uint32_t off = (uint32_t)((arow + mt * 16) * SPAD + acol) * 2u;
                ldsm_x4(ah[0], ah[1], ah[2], ah[3], aB + off);
                ldsm_x4(al[0], al[1], al[2], al[3], aB + 128 * SPAD * 2 + off);
#pragma unroll
                for (int nt = 0; nt < 8; nt++) mma16816(acc[mt][nt], ah, bh[nt]);
#pragma unroll
                for (int nt = 0; nt < 8; nt++) mma16816(acc[mt][nt], ah, bl[nt]);
#pragma unroll
                for (int nt = 0; nt < 8; nt++) mma16816(acc[mt][nt], al, bh[nt]);
            }
        }
    }

    // ---- Epilogue ----
    // D fragment: d0,d1 = (row lane/4, cols 2*(lane%4)+{0,1}); d2,d3 = row+8.
    const int cpair = 2 * (lane & 3);
    if (MODE == 1) {
#pragma unroll
        for (int mt = 0; mt < 2; mt++)
#pragma unroll
            for (int half = 0; half < 2; half++) {
                const int m = m0 + wm + mt * 16 + (lane >> 2) + half * 8;
                float* dst = outp + (size_t)m * DM_ + j0 + wn + cpair;
#pragma unroll
                for (int nt = 0; nt < 8; nt++)
                    *(float2*)(dst + nt * 8) =
                        make_float2(acc[mt][nt][2 * half], acc[mt][nt][2 * half + 1]);
            }
    } else {
        const int jb = j0 + wn;                     // multiple of 64 -> one head/warp-col
        const bool isV = (jb >= 2560);
        const bool isQ = (jb < 2048);
        const int head = isQ ? (jb >> 6) : (jb < 2560 ? ((jb - 2048) >> 6) : ((jb - 2560) >> 6));
        double invf[8];
        if (!isV) {
#pragma unroll
            for (int nt = 0; nt < 8; nt++) {
                const int pi = nt * 4 + (lane & 3); // rope pair index in head
                invf[nt] = exp2(-(2.0 * pi) * (LOG2_THETA / 64.0));
            }
        }
#pragma unroll
        for (int mt = 0; mt < 2; mt++)
#pragma unroll
            for (int half = 0; half < 2; half++) {
                const int m = m0 + wm + mt * 16 + (lane >> 2) + half * 8;
                const int bb = m >> 11;
                const int t  = m & (T_ - 1);
                if (isV) {
                    float* dst = g_V + (((size_t)bb * HKV_ + head) * T_ + t) * HD_ + cpair;
#pragma unroll
                    for (int nt = 0; nt < 8; nt++)
                        *(float2*)(dst + nt * 8) =
                            make_float2(acc[mt][nt][2 * half], acc[mt][nt][2 * half + 1]);
                } else {
                    const int p = pos[t];
                    float* dst = isQ
                        ? g_Q + (((size_t)bb * HQ_  + head) * T_ + t) * HD_ + cpair
                        : g_K + (((size_t)bb * HKV_ + head) * T_ + t) * HD_ + cpair;
#pragma unroll
                    for (int nt = 0; nt < 8; nt++) {
                        double sn, cs;
                        sincos((double)p * invf[nt], &sn, &cs);
                        const float fc = (float)cs, fs = (float)sn;
                        const float fe = acc[mt][nt][2 * half];
                        const float fo = acc[mt][nt][2 * half + 1];
                        *(float2*)(dst + nt * 8) =
                            make_float2(fe * fc - fo * fs, fe * fs + fo * fc);
                    }
                }
            }
    }
}

// ============================================================================
// Causal GQA flash attention, fp32 (proven at rel_err 3.6e-6).
// Epilogue now emits hi/lo bf16 for the out-projection.
// ============================================================================
#define ATTN_SMEM_FLOATS (64*128 + 64*64 + 64*68 + 128*65)

__global__ __launch_bounds__(128, 2)
void attn_kernel()
{
    extern __shared__ float sm[];
    float* Qs = sm;                        // [d][r]  64 x 128
    float* Ks = Qs + 64 * 128;             // [d][n]  64 x 64
    float* Vs = Ks + 64 * 64;              // [n][d]  64 x 68 (padded)
    float* Ps = Vs + 64 * 68;              // [r][n]  128 x 65 (padded)

    const int qt = (int)gridDim.x - 1 - (int)blockIdx.x;
    const int hq = blockIdx.y;
    const int bb = blockIdx.z;
    const int hk = hq >> 2;

    const int tid = threadIdx.x;
    const int ty = tid >> 3, tx = tid & 7;
    const int r0 = ty * 8, c0 = tx * 8;

    {
        const float* qsrc = g_Q + (((size_t)bb * HQ_ + hq) * T_ + (size_t)qt * 128 + tid) * HD_;
#pragma unroll
        for (int v = 0; v < 16; v++) {
            float4 q4 = *(const float4*)(qsrc + 4 * v);
            Qs[(4 * v + 0) * 128 + tid] = q4.x * 0.125f;
            Qs[(4 * v + 1) * 128 + tid] = q4.y * 0.125f;
            Qs[(4 * v + 2) * 128 + tid] = q4.z * 0.125f;
            Qs[(4 * v + 3) * 128 + tid] = q4.w * 0.125f;
        }
    }

    float O[8][8];
#pragma unroll
    for (int i = 0; i < 8; i++)
#pragma unroll
        for (int j = 0; j < 8; j++) O[i][j] = 0.f;
    float m_st[8], l_st[8];
#pragma unroll
    for (int i = 0; i < 8; i++) { m_st[i] = -FLT_MAX; l_st[i] = 0.f; }

    const float* kbase = g_K + ((size_t)bb * HKV_ + hk) * T_ * HD_;
    const float* vbase = g_V + ((size_t)bb * HKV_ + hk) * T_ * HD_;

    const int nrow  = tid >> 1;
    const int dpart = (tid & 1) * 32;
    const int ktmax = 2 * qt + 1;

    for (int kt = 0; kt <= ktmax; kt++) {
        __syncthreads();
        {
            const float* ksrc = kbase + ((size_t)kt * 64 + nrow) * HD_ + dpart;
            const float* vsrc = vbase + ((size_t)kt * 64 + nrow) * HD_ + dpart;
#pragma unroll
            for (int v = 0; v < 8; v++) {
                float4 k4 = *(const float4*)(ksrc + 4 * v);
                int d = dpart + 4 * v;
                Ks[(d + 0) * 64 + nrow] = k4.x;
                Ks[(d + 1) * 64 + nrow] = k4.y;
                Ks[(d + 2) * 64 + nrow] = k4.z;
                Ks[(d + 3) * 64 + nrow] = k4.w;
                *(float4*)&Vs[nrow * 68 + dpart + 4 * v] = *(const float4*)(vsrc + 4 * v);
            }
        }
        __syncthreads();

        float S[8][8];
#pragma unroll
        for (int i = 0; i < 8; i++)
#pragma unroll
            for (int j = 0; j < 8; j++) S[i][j] = 0.f;
#pragma unroll 8
        for (int kk = 0; kk < 64; kk++) {
            float4 a0 = *(const float4*)&Qs[kk * 128 + r0];
            float4 a1 = *(const float4*)&Qs[kk * 128 + r0 + 4];
            float4 b0 = *(const float4*)&Ks[kk * 64 + c0];
            float4 b1 = *(const float4*)&Ks[kk * 64 + c0 + 4];
            float a[8] = {a0.x, a0.y, a0.z, a0.w, a1.x, a1.y, a1.z, a1.w};
            float b[8] = {b0.x, b0.y, b0.z, b0.w, b1.x, b1.y, b1.z, b1.w};
#pragma unroll
            for (int i = 0; i < 8; i++)
#pragma unroll
                for (int j = 0; j < 8; j++)
                    S[i][j] = fmaf(a[i], b[j], S[i][j]);
        }

        if (kt >= 2 * qt) {
            int qg0 = qt * 128 + r0;
            int kg0 = kt * 64 + c0;
#pragma unroll
            for (int i = 0; i < 8; i++)
#pragma unroll
                for (int j = 0; j < 8; j++)
                    if (kg0 + j > qg0 + i) S[i][j] = -FLT_MAX;
        }

#pragma unroll
        for (int i = 0; i < 8; i++) {
            float mx = S[i][0];
#pragma unroll
            for (int j = 1; j < 8; j++) mx = fmaxf(mx, S[i][j]);
            mx = fmaxf(mx, __shfl_xor_sync(0xffffffffu, mx, 1));
            mx = fmaxf(mx, __shfl_xor_sync(0xffffffffu, mx, 2));
            mx = fmaxf(mx, __shfl_xor_sync(0xffffffffu, mx, 4));
            float nm = fmaxf(m_st[i], mx);
            float sum = 0.f;
#pragma unroll
            for (int j = 0; j < 8; j++) {
                S[i][j] = __expf(S[i][j] - nm);
                sum += S[i][j];
            }
            sum += __shfl_xor_sync(0xffffffffu, sum, 1);
            sum += __shfl_xor_sync(0xffffffffu, sum, 2);
            sum += __shfl_xor_sync(0xffffffffu, sum, 4);
            float corr = __expf(m_st[i] - nm);
            m_st[i] = nm;
            l_st[i] = l_st[i] * corr + sum;
#pragma unroll
            for (int j = 0; j < 8; j++) O[i][j] *= corr;
            float* prow = &Ps[(r0 + i) * 65 + c0];
#pragma unroll
            for (int j = 0; j < 8; j++) prow[j] = S[i][j];
        }
        __syncthreads();

#pragma unroll 4
        for (int n = 0; n < 64; n++) {
            float4 v0 = *(const float4*)&Vs[n * 68 + c0];
            float4 v1 = *(const float4*)&Vs[n * 68 + c0 + 4];
            float vv[8] = {v0.x, v0.y, v0.z, v0.w, v1.x, v1.y, v1.z, v1.w};
#pragma unroll
            for (int i = 0; i < 8; i++) {
                float a = Ps[(r0 + i) * 65 + n];
#pragma unroll
                for (int j = 0; j < 8; j++)
                    O[i][j] = fmaf(a, vv[j], O[i][j]);
            }
        }
    }

    // Finalize: O /= l, emit hi/lo bf16 rows for the out-projection GEMM.
#pragma unroll
    for (int i = 0; i < 8; i++) {
        const float inv = 1.0f / l_st[i];
        const size_t row = (size_t)bb * T_ + (size_t)qt * 128 + r0 + i;
        const size_t off = row * DM_ + hq * HD_ + c0;
        uint4 uh, ul;
        uint32_t* ph = (uint32_t*)&uh;
        uint32_t* pl = (uint32_t*)&ul;
#pragma unroll
        for (int q = 0; q < 4; q++) {
            __nv_bfloat16 h0, h1, l0, l1;
            split1(O[i][2 * q]     * inv, h0, l0);
            split1(O[i][2 * q + 1] * inv, h1, l1);
            ph[q] = (uint32_t)__bfloat16_as_ushort(h0) | ((uint32_t)__bfloat16_as_ushort(h1) << 16);
            pl[q] = (uint32_t)__bfloat16_as_ushort(l0) | ((uint32_t)__bfloat16_as_ushort(l1) << 16);
        }
        *(uint4*)(g_Ohi + off) = uh;
        *(uint4*)(g_Olo + off) = ul;
    }
}

// ============================================================================
extern "C" void kernel_launch(void* const* d_in, const int* in_sizes, int n_in,
                              void* d_out, int out_size)
{
    const float* x   = (const float*)d_in[0];
    const int*   pos = (const int*)  d_in[1];
    const float* WQ  = (const float*)d_in[2];
    const float* WK  = (const float*)d_in[3];
    const float* WV  = (const float*)d_in[4];
    const float* WO  = (const float*)d_in[5];
    float* out = (float*)d_out;

    cudaFuncSetAttribute(attn_kernel, cudaFuncAttributeMaxDynamicSharedMemorySize,
                         ATTN_SMEM_FLOATS * (int)sizeof(float));

    // 0) hi/lo bf16 conversion of x and all weights
    cvt_kernel<<<CVT_TOTAL_F4 / 256, 256>>>(x, WQ, WK, WV, WO);

    // 1) QKV projection + RoPE (tensor cores): 3072 cols -> 24 N-tiles
    gemm_mma_kernel<0><<<dim3(24, (B_ * T_) / 128), 256>>>(pos, nullptr);

    // 2) Flash attention (fp32), emits hi/lo bf16
    attn_kernel<<<dim3(T_ / 128, HQ_, B_), 128, ATTN_SMEM_FLOATS * (int)sizeof(float)>>>();

    // 3) Output projection (tensor cores): 2048 cols -> 16 N-tiles
    gemm_mma_kernel<1><<<dim3(16, (B_ * T_) / 128), 256>>>(pos, out);
}

// round 8
// speedup vs baseline: 2.3868x; 1.5242x over previous
#include <cuda_runtime.h>
#include <cuda_bf16.h>
#include <math.h>
#include <float.h>
#include <stdint.h>

// Problem constants
#define B_    2
#define T_    2048
#define DM_   2048
#define HQ_   32
#define HKV_  8
#define HD_   64
#define LOG2_THETA 13.287712379549449

// bf16 hi/lo split buffers (no allocs -> __device__ globals)
__device__ __nv_bfloat16 g_xhi[(size_t)4096 * 2048];
__device__ __nv_bfloat16 g_xlo[(size_t)4096 * 2048];
__device__ __nv_bfloat16 g_Whi[(size_t)3072 * 2048];   // WQ|WK|WV rows
__device__ __nv_bfloat16 g_Wlo[(size_t)3072 * 2048];
__device__ __nv_bfloat16 g_WOhi[(size_t)2048 * 2048];
__device__ __nv_bfloat16 g_WOlo[(size_t)2048 * 2048];
__device__ __nv_bfloat16 g_Ohi[(size_t)4096 * 2048];   // attention out
__device__ __nv_bfloat16 g_Olo[(size_t)4096 * 2048];
__device__ __nv_bfloat16 g_Qhi[(size_t)B_ * HQ_  * T_ * HD_];  // rope'd, pre-scaled
__device__ __nv_bfloat16 g_Qlo[(size_t)B_ * HQ_  * T_ * HD_];
__device__ __nv_bfloat16 g_Khi[(size_t)B_ * HKV_ * T_ * HD_];  // rope'd
__device__ __nv_bfloat16 g_Klo[(size_t)B_ * HKV_ * T_ * HD_];
__device__ __nv_bfloat16 g_Vhi[(size_t)B_ * HKV_ * T_ * HD_];
__device__ __nv_bfloat16 g_Vlo[(size_t)B_ * HKV_ * T_ * HD_];

// ============================================================================
// PTX helpers (legacy tensor path: plain PTX, valid on compute_103)
// ============================================================================
__device__ __forceinline__ uint32_t smem_u32(const void* p) {
    uint32_t a;
    asm("{ .reg .u64 t; cvta.to.shared.u64 t, %1; cvt.u32.u64 %0, t; }"
        : "=r"(a) : "l"(p));
    return a;
}
__device__ __forceinline__ void ldsm_x4(uint32_t& r0, uint32_t& r1,
                                        uint32_t& r2, uint32_t& r3, uint32_t a) {
    asm volatile("ldmatrix.sync.aligned.m8n8.x4.shared.b16 {%0,%1,%2,%3}, [%4];"
                 : "=r"(r0), "=r"(r1), "=r"(r2), "=r"(r3) : "r"(a));
}
__device__ __forceinline__ void ldsm_x4_t(uint32_t& r0, uint32_t& r1,
                                          uint32_t& r2, uint32_t& r3, uint32_t a) {
    asm volatile("ldmatrix.sync.aligned.m8n8.x4.trans.shared.b16 {%0,%1,%2,%3}, [%4];"
                 : "=r"(r0), "=r"(r1), "=r"(r2), "=r"(r3) : "r"(a));
}
__device__ __forceinline__ void mma16816(float* d, const uint32_t* a, const uint32_t* b) {
    asm volatile(
        "mma.sync.aligned.m16n8k16.row.col.f32.bf16.bf16.f32 "
        "{%0,%1,%2,%3}, {%4,%5,%6,%7}, {%8,%9}, {%0,%1,%2,%3};"
        : "+f"(d[0]), "+f"(d[1]), "+f"(d[2]), "+f"(d[3])
        : "r"(a[0]), "r"(a[1]), "r"(a[2]), "r"(a[3]), "r"(b[0]), "r"(b[1]));
}
__device__ __forceinline__ void split1(float v, __nv_bfloat16& h, __nv_bfloat16& l) {
    h = __float2bfloat16_rn(v);
    l = __float2bfloat16_rn(v - __bfloat162float(h));
}
// pack (a,b) -> hi bf16x2 (returned) + lo bf16x2 (out param)
__device__ __forceinline__ uint32_t pack_hl(float a, float b, uint32_t& lo) {
    __nv_bfloat16 ha, hb, la, lb;
    split1(a, ha, la);
    split1(b, hb, lb);
    lo = (uint32_t)__bfloat16_as_ushort(la) | ((uint32_t)__bfloat16_as_ushort(lb) << 16);
    return (uint32_t)__bfloat16_as_ushort(ha) | ((uint32_t)__bfloat16_as_ushort(hb) << 16);
}

// ============================================================================
// Kernel 0: fp32 -> (hi, lo) bf16 conversion for x, WQ|WK|WV, WO.
// ============================================================================
#define NE_X   8388608ull
#define NE_WQ  4194304ull
#define NE_WKV 1048576ull
#define CVT_TOTAL_F4 4718592

__global__ __launch_bounds__(256)
void cvt_kernel(const float* __restrict__ x,  const float* __restrict__ WQ,
                const float* __restrict__ WK, const float* __restrict__ WV,
                const float* __restrict__ WO)
{
    const size_t e = ((size_t)blockIdx.x * 256 + threadIdx.x) * 4;
    const float* src; __nv_bfloat16 *dh, *dl; size_t off;
    if (e < NE_X)                          { src = x;  dh = g_xhi;            dl = g_xlo;            off = e; }
    else if (e < NE_X + NE_WQ)             { src = WQ; dh = g_Whi;            dl = g_Wlo;            off = e - NE_X; }
    else if (e < NE_X + NE_WQ + NE_WKV)    { src = WK; dh = g_Whi + 4194304;  dl = g_Wlo + 4194304;  off = e - NE_X - NE_WQ; }
    else if (e < NE_X + NE_WQ + 2*NE_WKV)  { src = WV; dh = g_Whi + 5242880;  dl = g_Wlo + 5242880;  off = e - NE_X - NE_WQ - NE_WKV; }
    else                                   { src = WO; dh = g_WOhi;           dl = g_WOlo;           off = e - NE_X - NE_WQ - 2*NE_WKV; }
    float4 v = *(const float4*)(src + off);
    uint2 uh, ul;
    uh.x = pack_hl(v.x, v.y, ul.x);
    uh.y = pack_hl(v.z, v.w, ul.y);
    *(uint2*)(dh + off) = uh;
    *(uint2*)(dl + off) = ul;
}

// ============================================================================
// mma.sync split-fp32 GEMM (proven R7):  D[128x128] = A * B^T, K=2048.
// MODE 0: QKV proj -> RoPE -> hi/lo bf16 Q/K/V (Q pre-scaled by 0.125).
// MODE 1: out proj -> fp32 to outp.
// ============================================================================
#define SPAD 40

template <int MODE>
__global__ __launch_bounds__(256)
void gemm_mma_kernel(const int* __restrict__ pos, float* __restrict__ outp)
{
    __shared__ __align__(16) __nv_bfloat16 sA[2][128 * SPAD];
    __shared__ __align__(16) __nv_bfloat16 sB[2][128 * SPAD];

    const int j0 = blockIdx.x * 128;
    const int m0 = blockIdx.y * 128;
    const int tid = threadIdx.x;
    const int wid = tid >> 5, lane = tid & 31;

    const __nv_bfloat16* Ahi = (MODE == 0) ? g_xhi : g_Ohi;
    const __nv_bfloat16* Alo = (MODE == 0) ? g_xlo : g_Olo;
    const __nv_bfloat16* Bhi = ((MODE == 0) ? g_Whi : g_WOhi) + (size_t)j0 * DM_;
    const __nv_bfloat16* Blo = ((MODE == 0) ? g_Wlo : g_WOlo) + (size_t)j0 * DM_;

    const int lrow = tid >> 1;
    const int lcol = (tid & 1) * 16;
    const size_t aoff = (size_t)(m0 + lrow) * DM_ + lcol;
    const size_t boff = (size_t)lrow * DM_ + lcol;

    const int wm = (wid & 3) * 32;
    const int wn = (wid >> 2) * 64;

    float acc[2][8][4];
#pragma unroll
    for (int mt = 0; mt < 2; mt++)
#pragma unroll
        for (int nt = 0; nt < 8; nt++)
#pragma unroll
            for (int q = 0; q < 4; q++) acc[mt][nt][q] = 0.f;

    const uint32_t aB = smem_u32(sA);
    const uint32_t bB = smem_u32(sB);
    const int sidx = lrow * SPAD + lcol;

    uint4 pa0 = *(const uint4*)(Ahi + aoff);
    uint4 pa1 = *(const uint4*)(Ahi + aoff + 8);
    uint4 pa2 = *(const uint4*)(Alo + aoff);
    uint4 pa3 = *(const uint4*)(Alo + aoff + 8);
    uint4 pb0 = *(const uint4*)(Bhi + boff);
    uint4 pb1 = *(const uint4*)(Bhi + boff + 8);
    uint4 pb2 = *(const uint4*)(Blo + boff);
    uint4 pb3 = *(const uint4*)(Blo + boff + 8);

    for (int kc = 0; kc < DM_ / 32; kc++) {
        __syncthreads();
        *(uint4*)&sA[0][sidx]     = pa0;
        *(uint4*)&sA[0][sidx + 8] = pa1;
        *(uint4*)&sA[1][sidx]     = pa2;
        *(uint4*)&sA[1][sidx + 8] = pa3;
        *(uint4*)&sB[0][sidx]     = pb0;
        *(uint4*)&sB[0][sidx + 8] = pb1;
        *(uint4*)&sB[1][sidx]     = pb2;
        *(uint4*)&sB[1][sidx + 8] = pb3;
        __syncthreads();

        if (kc + 1 < DM_ / 32) {
            const size_t nk = (size_t)(kc + 1) * 32;
            pa0 = *(const uint4*)(Ahi + aoff + nk);
            pa1 = *(const uint4*)(Ahi + aoff + nk + 8);
            pa2 = *(const uint4*)(Alo + aoff + nk);
            pa3 = *(const uint4*)(Alo + aoff + nk + 8);
            pb0 = *(const uint4*)(Bhi + boff + nk);
            pb1 = *(const uint4*)(Bhi + boff + nk + 8);
            pb2 = *(const uint4*)(Blo + boff + nk);
            pb3 = *(const uint4*)(Blo + boff + nk + 8);
        }

#pragma unroll
        for (int ks = 0; ks < 2; ks++) {
            uint32_t bh[8][2], bl[8][2];
            const int brow = wn + ((lane >> 4) & 1) * 8 + (lane & 7);
            const int bcol = ks * 16 + ((lane >> 3) & 1) * 8;
#pragma unroll
            for (int p = 0; p < 4; p++) {
                const uint32_t off = (uint32_t)((brow + p * 16) * SPAD + bcol) * 2u;
                ldsm_x4(bh[2*p][0], bh[2*p][1], bh[2*p+1][0], bh[2*p+1][1], bB + off);
                ldsm_x4(bl[2*p][0], bl[2*p][1], bl[2*p+1][0], bl[2*p+1][1],
                        bB + 128 * SPAD * 2 + off);
            }
            const int arow = wm + (lane & 15);
            const int acol = ks * 16 + (lane >> 4) * 8;
#pragma unroll
            for (int mt = 0; mt < 2; mt++) {
                uint32_t ah[4], al[4];
                const uint32_t off = (uint32_t)((arow + mt * 16) * SPAD + acol) * 2u;
                ldsm_x4(ah[0], ah[1], ah[2], ah[3], aB + off);
                ldsm_x4(al[0], al[1], al[2], al[3], aB + 128 * SPAD * 2 + off);
#pragma unroll
                for (int nt = 0; nt < 8; nt++) mma16816(acc[mt][nt], ah, bh[nt]);
#pragma unroll
                for (int nt = 0; nt < 8; nt++) mma16816(acc[mt][nt], ah, bl[nt]);
#pragma unroll
                for (int nt = 0; nt < 8; nt++) mma16816(acc[mt][nt], al, bh[nt]);
            }
        }
    }

    // ---- Epilogue ----
    const int cpair = 2 * (lane & 3);
    if (MODE == 1) {
#pragma unroll
        for (int mt = 0; mt < 2; mt++)
#pragma unroll
            for (int half = 0; half < 2; half++) {
                const int m = m0 + wm + mt * 16 + (lane >> 2) + half * 8;
                float* dst = outp + (size_t)m * DM_ + j0 + wn + cpair;
#pragma unroll
                for (int nt = 0; nt < 8; nt++)
                    *(float2*)(dst + nt * 8) =
                        make_float2(acc[mt][nt][2 * half], acc[mt][nt][2 * half + 1]);
            }
    } else {
        const int jb = j0 + wn;
        const bool isV = (jb >= 2560);
        const bool isQ = (jb < 2048);
        const int head = isQ ? (jb >> 6) : (jb < 2560 ? ((jb - 2048) >> 6) : ((jb - 2560) >> 6));
        double invf[8];
        if (!isV) {
#pragma unroll
            for (int nt = 0; nt < 8; nt++) {
                const int pi = nt * 4 + (lane & 3);
                invf[nt] = exp2(-(2.0 * pi) * (LOG2_THETA / 64.0));
            }
        }
#pragma unroll
        for (int mt = 0; mt < 2; mt++)
#pragma unroll
            for (int half = 0; half < 2; half++) {
                const int m = m0 + wm + mt * 16 + (lane >> 2) + half * 8;
                const int bb = m >> 11;
                const int t  = m & (T_ - 1);
                if (isV) {
                    const size_t doff =
                        (((size_t)bb * HKV_ + head) * T_ + t) * HD_ + cpair;
#pragma unroll
                    for (int nt = 0; nt < 8; nt++) {
                        uint32_t lo;
                        uint32_t hi = pack_hl(acc[mt][nt][2 * half],
                                              acc[mt][nt][2 * half + 1], lo);
                        *(uint32_t*)(g_Vhi + doff + nt * 8) = hi;
                        *(uint32_t*)(g_Vlo + doff + nt * 8) = lo;
                    }
                } else {
                    const int p = pos[t];
                    const float qs = isQ ? 0.125f : 1.0f;   // fold 1/sqrt(HD) into Q
                    const size_t doff = isQ
                        ? (((size_t)bb * HQ_  + head) * T_ + t) * HD_ + cpair
                        : (((size_t)bb * HKV_ + head) * T_ + t) * HD_ + cpair;
                    __nv_bfloat16* dsth = isQ ? g_Qhi : g_Khi;
                    __nv_bfloat16* dstl = isQ ? g_Qlo : g_Klo;
#pragma unroll
                    for (int nt = 0; nt < 8; nt++) {
                        double sn, cs;
                        sincos((double)p * invf[nt], &sn, &cs);
                        const float fc = (float)cs, fs = (float)sn;
                        const float fe = acc[mt][nt][2 * half];
                        const float fo = acc[mt][nt][2 * half + 1];
                        uint32_t lo;
                        uint32_t hi = pack_hl((fe * fc - fo * fs) * qs,
                                              (fe * fs + fo * fc) * qs, lo);
                        *(uint32_t*)(dsth + doff + nt * 8) = hi;
                        *(uint32_t*)(dstl + doff + nt * 8) = lo;
                    }
                }
            }
    }
}

// ============================================================================
// Causal GQA flash attention on tensor cores (mma.sync, split-fp32).
// 128 threads = 4 warps; BM=128 (32 rows/warp), BN=64, HD=64.
// S: 3 passes (Qhi.Khi + Qhi.Klo + Qlo.Khi); PV: 3 passes (Phi.Vhi+Phi.Vlo+Plo.Vhi).
// P stays in registers: C-frag of S == A-frag of PV after bf16x2 packing.
// Smem stride 72 bf16 (144B -> +4 banks/row) => conflict-free ldmatrix.
// 72 KB dyn smem -> 2 CTAs/SM.
// ============================================================================
#define APAD 72
#define ATTN_SMEM_BYTES ((128 * APAD * 2 + 64 * APAD * 4) * 2)

__global__ __launch_bounds__(128, 2)
void attn_mma_kernel()
{
    extern __shared__ __nv_bfloat16 smb[];
    __nv_bfloat16* Qh = smb;                   // [128][APAD]
    __nv_bfloat16* Ql = Qh + 128 * APAD;
    __nv_bfloat16* Kh = Ql + 128 * APAD;       // [64][APAD]
    __nv_bfloat16* Kl = Kh + 64 * APAD;
    __nv_bfloat16* Vh = Kl + 64 * APAD;
    __nv_bfloat16* Vl = Vh + 64 * APAD;

    const int qt = (int)gridDim.x - 1 - (int)blockIdx.x;
    const int hq = blockIdx.y;
    const int bb = blockIdx.z;
    const int hk = hq >> 2;

    const int tid = threadIdx.x;
    const int wid = tid >> 5, lane = tid & 31;
    const int wm = wid * 32;
    const int gID = lane >> 2, tig = lane & 3;

    const uint32_t QhB = smem_u32(Qh), QlB = smem_u32(Ql);
    const uint32_t KhB = smem_u32(Kh), KlB = smem_u32(Kl);
    const uint32_t VhB = smem_u32(Vh), VlB = smem_u32(Vl);

    // Load Q tile (hi/lo): one 64-elem row per thread
    {
        const size_t qoff = (((size_t)bb * HQ_ + hq) * T_ + (size_t)qt * 128 + tid) * HD_;
#pragma unroll
        for (int v = 0; v < 8; v++) {
            *(uint4*)&Qh[tid * APAD + v * 8] = *(const uint4*)(g_Qhi + qoff + v * 8);
            *(uint4*)&Ql[tid * APAD + v * 8] = *(const uint4*)(g_Qlo + qoff + v * 8);
        }
    }

    float O[2][8][4];
#pragma unroll
    for (int mt = 0; mt < 2; mt++)
#pragma unroll
        for (int nt = 0; nt < 8; nt++)
#pragma unroll
            for (int q = 0; q < 4; q++) O[mt][nt][q] = 0.f;
    float m_st[2][2], l_st[2][2];
#pragma unroll
    for (int mt = 0; mt < 2; mt++)
#pragma unroll
        for (int h2 = 0; h2 < 2; h2++) { m_st[mt][h2] = -FLT_MAX; l_st[mt][h2] = 0.f; }

    const size_t kvbase = ((size_t)bb * HKV_ + hk) * T_ * HD_;
    const int lrow = tid >> 1;
    const int lhalf = (tid & 1) * 32;
    const int ktmax = 2 * qt + 1;

    for (int kt = 0; kt <= ktmax; kt++) {
        __syncthreads();   // WAR vs previous iteration's ldsm reads
        {
            const size_t goff = kvbase + ((size_t)kt * 64 + lrow) * HD_ + lhalf;
            const int soff = lrow * APAD + lhalf;
#pragma unroll
            for (int v = 0; v < 4; v++) {
                *(uint4*)&Kh[soff + v * 8] = *(const uint4*)(g_Khi + goff + v * 8);
                *(uint4*)&Kl[soff + v * 8] = *(const uint4*)(g_Klo + goff + v * 8);
                *(uint4*)&Vh[soff + v * 8] = *(const uint4*)(g_Vhi + goff + v * 8);
                *(uint4*)&Vl[soff + v * 8] = *(const uint4*)(g_Vlo + goff + v * 8);
            }
        }
        __syncthreads();

        // ---- S = Q K^T (3 passes) ----
        float S[2][8][4];
#pragma unroll
        for (int mt = 0; mt < 2; mt++)
#pragma unroll
            for (int nt = 0; nt < 8; nt++)
#pragma unroll
                for (int q = 0; q < 4; q++) S[mt][nt][q] = 0.f;

#pragma unroll
        for (int ks = 0; ks < 4; ks++) {
            uint32_t bh[8][2], bl[8][2];
            const int brow = ((lane >> 4) & 1) * 8 + (lane & 7);
            const int bcol = ks * 16 + ((lane >> 3) & 1) * 8;
#pragma unroll
            for (int p = 0; p < 4; p++) {
                const uint32_t off = (uint32_t)((brow + p * 16) * APAD + bcol) * 2u;
                ldsm_x4(bh[2*p][0], bh[2*p][1], bh[2*p+1][0], bh[2*p+1][1], KhB + off);
                ldsm_x4(bl[2*p][0], bl[2*p][1], bl[2*p+1][0], bl[2*p+1][1], KlB + off);
            }
            const int arow = wm + (lane & 15);
            const int acol = ks * 16 + (lane >> 4) * 8;
#pragma unroll
            for (int mt = 0; mt < 2; mt++) {
                uint32_t ah[4], al[4];
                const uint32_t off = (uint32_t)((arow + mt * 16) * APAD + acol) * 2u;
                ldsm_x4(ah[0], ah[1], ah[2], ah[3], QhB + off);
                ldsm_x4(al[0], al[1], al[2], al[3], QlB + off);
#pragma unroll
                for (int nt = 0; nt < 8; nt++) mma16816(S[mt][nt], ah, bh[nt]);
#pragma unroll
                for (int nt = 0; nt < 8; nt++) mma16816(S[mt][nt], ah, bl[nt]);
#pragma unroll
                for (int nt = 0; nt < 8; nt++) mma16816(S[mt][nt], al, bh[nt]);
            }
        }

        // ---- Causal mask (diagonal tiles only) ----
        if (kt >= 2 * qt) {
            const int rg = qt * 128 + wm + gID;
            const int cg = kt * 64 + 2 * tig;
#pragma unroll
            for (int mt = 0; mt < 2; mt++)
#pragma unroll
                for (int nt = 0; nt < 8; nt++)
#pragma unroll
                    for (int h2 = 0; h2 < 2; h2++)
#pragma unroll
                        for (int e = 0; e < 2; e++)
                            if (cg + nt * 8 + e > rg + mt * 16 + h2 * 8)
                                S[mt][nt][2 * h2 + e] = -FLT_MAX;
        }

        // ---- Online softmax (rows: quad-local, shfl_xor 1,2) ----
#pragma unroll
        for (int mt = 0; mt < 2; mt++)
#pragma unroll
            for (int h2 = 0; h2 < 2; h2++) {
                float mx = -FLT_MAX;
#pragma unroll
                for (int nt = 0; nt < 8; nt++)
                    mx = fmaxf(mx, fmaxf(S[mt][nt][2 * h2], S[mt][nt][2 * h2 + 1]));
                mx = fmaxf(mx, __shfl_xor_sync(0xffffffffu, mx, 1));
                mx = fmaxf(mx, __shfl_xor_sync(0xffffffffu, mx, 2));
                const float nm = fmaxf(m_st[mt][h2], mx);
                float sum = 0.f;
#pragma unroll
                for (int nt = 0; nt < 8; nt++) {
                    S[mt][nt][2 * h2]     = __expf(S[mt][nt][2 * h2]     - nm);
                    S[mt][nt][2 * h2 + 1] = __expf(S[mt][nt][2 * h2 + 1] - nm);
                    sum += S[mt][nt][2 * h2] + S[mt][nt][2 * h2 + 1];
                }
                sum += __shfl_xor_sync(0xffffffffu, sum, 1);
                sum += __shfl_xor_sync(0xffffffffu, sum, 2);
                const float corr = __expf(m_st[mt][h2] - nm);
                m_st[mt][h2] = nm;
                l_st[mt][h2] = l_st[mt][h2] * corr + sum;
#pragma unroll
                for (int nt = 0; nt < 8; nt++) {
                    O[mt][nt][2 * h2]     *= corr;
                    O[mt][nt][2 * h2 + 1] *= corr;
                }
            }

        // ---- O += P V (3 passes; P packed register-locally) ----
#pragma unroll
        for (int ks = 0; ks < 4; ks++) {
            uint32_t vh[8][2], vl[8][2];
            const int vrow = ks * 16 + (lane & 15);
#pragma unroll
            for (int p = 0; p < 4; p++) {
                const uint32_t off =
                    (uint32_t)(vrow * APAD + p * 16 + (lane >> 4) * 8) * 2u;
                ldsm_x4_t(vh[2*p][0], vh[2*p][1], vh[2*p+1][0], vh[2*p+1][1], VhB + off);
                ldsm_x4_t(vl[2*p][0], vl[2*p][1], vl[2*p+1][0], vl[2*p+1][1], VlB + off);
            }
#pragma unroll
            for (int mt = 0; mt < 2; mt++) {
                uint32_t ah[4], al[4];
                ah[0] = pack_hl(S[mt][2*ks][0],   S[mt][2*ks][1],   al[0]);
                ah[1] = pack_hl(S[mt][2*ks][2],   S[mt][2*ks][3],   al[1]);
                ah[2] = pack_hl(S[mt][2*ks+1][0], S[mt][2*ks+1][1], al[2]);
                ah[3] = pack_hl(S[mt][2*ks+1][2], S[mt][2*ks+1][3], al[3]);
#pragma unroll
                for (int nt = 0; nt < 8; nt++) mma16816(O[mt][nt], ah, vh[nt]);
#pragma unroll
                for (int nt = 0; nt < 8; nt++) mma16816(O[mt][nt], ah, vl[nt]);
#pragma unroll
                for (int nt = 0; nt < 8; nt++) mma16816(O[mt][nt], al, vh[nt]);
            }
        }
    }

    // ---- Finalize: /l, split hi/lo, store for out-projection ----
#pragma unroll
    for (int mt = 0; mt < 2; mt++)
#pragma unroll
        for (int h2 = 0; h2 < 2; h2++) {
            const float inv = 1.0f / l_st[mt][h2];
            const int rg = qt * 128 + wm + mt * 16 + gID + h2 * 8;
            const size_t off = ((size_t)bb * T_ + rg) * DM_ + hq * HD_ + 2 * tig;
#pragma unroll
            for (int nt = 0; nt < 8; nt++) {
                uint32_t lo;
                uint32_t hi = pack_hl(O[mt][nt][2 * h2] * inv,
                                      O[mt][nt][2 * h2 + 1] * inv, lo);
                *(uint32_t*)(g_Ohi + off + nt * 8) = hi;
                *(uint32_t*)(g_Olo + off + nt * 8) = lo;
            }
        }
}

// ============================================================================
extern "C" void kernel_launch(void* const* d_in, const int* in_sizes, int n_in,
                              void* d_out, int out_size)
{
    const float* x   = (const float*)d_in[0];
    const int*   pos = (const int*)  d_in[1];
    const float* WQ  = (const float*)d_in[2];
    const float* WK  = (const float*)d_in[3];
    const float* WV  = (const float*)d_in[4];
    const float* WO  = (const float*)d_in[5];
    float* out = (float*)d_out;

    cudaFuncSetAttribute(attn_mma_kernel, cudaFuncAttributeMaxDynamicSharedMemorySize,
                         ATTN_SMEM_BYTES);

    // 0) hi/lo bf16 conversion of x and all weights
    cvt_kernel<<<CVT_TOTAL_F4 / 256, 256>>>(x, WQ, WK, WV, WO);

    // 1) QKV projection + RoPE (tensor cores) -> bf16 hi/lo Q/K/V
    gemm_mma_kernel<0><<<dim3(24, (B_ * T_) / 128), 256>>>(pos, nullptr);

    // 2) Flash attention (tensor cores, split-fp32) -> bf16 hi/lo O
    attn_mma_kernel<<<dim3(T_ / 128, HQ_, B_), 128, ATTN_SMEM_BYTES>>>();

    // 3) Output projection (tensor cores) -> fp32 out
    gemm_mma_kernel<1><<<dim3(16, (B_ * T_) / 128), 256>>>(pos, out);
}